// round 2
// baseline (speedup 1.0000x reference)
#include <cuda_runtime.h>
#include <cstdint>

// Problem constants (fixed shapes in this registry entry)
#define MAX_NODES 100000
#define D_FEAT 64

// Scratch accumulators: ~77 MB total, fits in GB300's ~126 MB L2, so the
// atomic RMW traffic should stay L2-resident between kernels.
// 16B alignment required for red.global.add.v4.f32.
__device__ __align__(16) float        g_sum[MAX_NODES * D_FEAT];
__device__ __align__(16) float        g_sq [MAX_NODES * D_FEAT];
__device__ __align__(16) unsigned int g_mx [MAX_NODES * D_FEAT];
__device__ unsigned int g_cnt[MAX_NODES];

// Order-preserving float -> uint map (monotonic): allows atomicMax on uint.
__device__ __forceinline__ unsigned int float_to_ordered(float f) {
    unsigned int u = __float_as_uint(f);
    return (u & 0x80000000u) ? ~u : (u | 0x80000000u);
}
__device__ __forceinline__ float ordered_to_float(unsigned int e) {
    return (e & 0x80000000u) ? __uint_as_float(e & 0x7FFFFFFFu)
                             : __uint_as_float(~e);
}

__global__ void init_kernel(int n_nodes) {
    int i = blockIdx.x * blockDim.x + threadIdx.x;
    int total = n_nodes * D_FEAT;
    if (i < total) {
        g_sum[i] = 0.0f;
        g_sq[i]  = 0.0f;
        g_mx[i]  = 0u;          // below encoding of any finite float
    }
    if (i < n_nodes) g_cnt[i] = 0u;
}

// One edge handled by 16 threads; each thread owns one float4 (4 features).
// Loads are fully coalesced: 16 threads x 16B = 256B per edge row.
// dst is int32 (JAX default config downgrades int64 -> int32).
__global__ void scatter_kernel(const float4* __restrict__ msg,
                               const int* __restrict__ dst,
                               int n_edges, int n_nodes) {
    int tid = blockIdx.x * blockDim.x + threadIdx.x;
    int e = tid >> 4;
    if (e >= n_edges) return;
    int c = tid & 15;

    int d = dst[e];
    if (d < 0 || d >= n_nodes) return;           // safety: degrade, don't crash

    float4 m = msg[(size_t)e * 16 + c];

    size_t base = (size_t)d * D_FEAT + (size_t)c * 4;

    // Vector reduction: sum
    float* sp = &g_sum[base];
    asm volatile("red.global.add.v4.f32 [%0], {%1, %2, %3, %4};"
                 :: "l"(sp), "f"(m.x), "f"(m.y), "f"(m.z), "f"(m.w) : "memory");

    // Vector reduction: sum of squares
    float* qp = &g_sq[base];
    asm volatile("red.global.add.v4.f32 [%0], {%1, %2, %3, %4};"
                 :: "l"(qp), "f"(m.x * m.x), "f"(m.y * m.y),
                    "f"(m.z * m.z), "f"(m.w * m.w) : "memory");

    // Max: scalar atomics on ordered-uint encoding (no vector max exists)
    unsigned int* mp = &g_mx[base];
    atomicMax(mp + 0, float_to_ordered(m.x));
    atomicMax(mp + 1, float_to_ordered(m.y));
    atomicMax(mp + 2, float_to_ordered(m.z));
    atomicMax(mp + 3, float_to_ordered(m.w));

    // Degree count: one per edge
    if (c == 0) atomicAdd(&g_cnt[d], 1u);
}

// One thread per (node, feature): compute mean/max/std and write the
// concatenated [N, 4*D] output.
__global__ void finalize_kernel(float* __restrict__ out, int n_nodes) {
    int tid = blockIdx.x * blockDim.x + threadIdx.x;
    int total = n_nodes * D_FEAT;
    if (tid >= total) return;

    int node = tid >> 6;           // D_FEAT = 64
    int f    = tid & 63;

    unsigned int deg_raw = g_cnt[node];
    float deg = deg_raw ? (float)deg_raw : 1.0f;   // clamp >= 1

    float s    = g_sum[tid];
    float mean = s / deg;
    float sq   = g_sq[tid];
    // var = E[x^2] - mean^2; clamp >= 0 against rounding (deg=1 cancellation)
    float var  = fmaxf(sq / deg - mean * mean, 0.0f);
    float sd   = sqrtf(var + 1e-8f);

    float mx = 0.0f;                                // empty segments -> 0
    if (deg_raw) mx = ordered_to_float(g_mx[tid]);

    size_t base = (size_t)node * (4 * D_FEAT) + f;
    out[base]               = s;
    out[base +     D_FEAT]  = mean;
    out[base + 2 * D_FEAT]  = mx;
    out[base + 3 * D_FEAT]  = sd;
}

extern "C" void kernel_launch(void* const* d_in, const int* in_sizes, int n_in,
                              void* d_out, int out_size) {
    const float* msg = (const float*)d_in[0];
    const int*   dst = (const int*)d_in[1];
    int n_edges = in_sizes[1];
    int n_nodes = out_size / (4 * D_FEAT);
    if (n_nodes > MAX_NODES) n_nodes = MAX_NODES;

    int init_total = n_nodes * D_FEAT;
    init_kernel<<<(init_total + 511) / 512, 512>>>(n_nodes);

    long long scatter_threads = (long long)n_edges * 16;
    int scatter_blocks = (int)((scatter_threads + 255) / 256);
    scatter_kernel<<<scatter_blocks, 256>>>((const float4*)msg, dst, n_edges, n_nodes);

    finalize_kernel<<<(init_total + 255) / 256, 256>>>((float*)d_out, n_nodes);
}

// round 3
// speedup vs baseline: 2.9252x; 2.9252x over previous
#include <cuda_runtime.h>
#include <cstdint>

#define MAX_NODES 100000
#define MAX_EDGES 1600000
#define D_FEAT 64

// ---- scratch (no feature-sized accumulators needed anymore) ----
__device__ unsigned int g_cnt        [MAX_NODES];
__device__ unsigned int g_offsets    [MAX_NODES + 1];
__device__ unsigned int g_cursor     [MAX_NODES];
__device__ unsigned int g_block_sums [256];
__device__ int          g_edge_sorted[MAX_EDGES];

// ---------------- pass 1: histogram ----------------
__global__ void zero_cnt_kernel(int n_nodes) {
    int i = blockIdx.x * blockDim.x + threadIdx.x;
    if (i < n_nodes) g_cnt[i] = 0u;
}

__global__ void hist_kernel(const int* __restrict__ dst, int n_edges, int n_nodes) {
    int e = blockIdx.x * blockDim.x + threadIdx.x;
    if (e >= n_edges) return;
    int d = dst[e];
    if ((unsigned)d < (unsigned)n_nodes) atomicAdd(&g_cnt[d], 1u);
}

// ---------------- pass 2: exclusive prefix scan over g_cnt ----------------
// scan1: per-block exclusive scan -> g_offsets, block totals -> g_block_sums
__global__ void scan1_kernel(int n_nodes) {
    __shared__ unsigned int sm[512];
    int i = blockIdx.x * 512 + threadIdx.x;
    unsigned int v = (i < n_nodes) ? g_cnt[i] : 0u;
    sm[threadIdx.x] = v;
    __syncthreads();
    for (int off = 1; off < 512; off <<= 1) {
        unsigned int t = (threadIdx.x >= off) ? sm[threadIdx.x - off] : 0u;
        __syncthreads();
        if (threadIdx.x >= off) sm[threadIdx.x] += t;
        __syncthreads();
    }
    if (i < n_nodes) g_offsets[i] = sm[threadIdx.x] - v;   // exclusive
    if (threadIdx.x == 511) g_block_sums[blockIdx.x] = sm[511];
}

// scan2: single block scans block sums (exclusive, in place). nblocks <= 256.
__global__ void scan2_kernel(int nblocks) {
    __shared__ unsigned int sm[256];
    unsigned int v = (threadIdx.x < (unsigned)nblocks) ? g_block_sums[threadIdx.x] : 0u;
    sm[threadIdx.x] = v;
    __syncthreads();
    for (int off = 1; off < 256; off <<= 1) {
        unsigned int t = (threadIdx.x >= off) ? sm[threadIdx.x - off] : 0u;
        __syncthreads();
        if (threadIdx.x >= off) sm[threadIdx.x] += t;
        __syncthreads();
    }
    if (threadIdx.x < (unsigned)nblocks) g_block_sums[threadIdx.x] = sm[threadIdx.x] - v;
}

// scan3: add block offsets; init cursor; set sentinel offsets[n] = n_edges
__global__ void scan3_kernel(int n_nodes, int n_edges) {
    int i = blockIdx.x * 512 + threadIdx.x;
    if (i < n_nodes) {
        unsigned int o = g_offsets[i] + g_block_sums[blockIdx.x];
        g_offsets[i] = o;
        g_cursor[i]  = o;
    }
    if (i == 0) g_offsets[n_nodes] = (unsigned int)n_edges;
}

// ---------------- pass 3: scatter edge ids into sorted order ----------------
__global__ void scatter_ids_kernel(const int* __restrict__ dst, int n_edges, int n_nodes) {
    int e = blockIdx.x * blockDim.x + threadIdx.x;
    if (e >= n_edges) return;
    int d = dst[e];
    if ((unsigned)d >= (unsigned)n_nodes) return;
    unsigned int pos = atomicAdd(&g_cursor[d], 1u);
    g_edge_sorted[pos] = e;
}

// ---------------- pass 4: gather + reduce in registers ----------------
// One warp per node. Each half-warp (16 lanes) processes one edge per
// iteration: lane c loads float4 = features [4c, 4c+4). Halves combined via
// shfl.xor(16) at the end. Output row written directly.
__global__ void gather_kernel(const float4* __restrict__ msg,
                              float* __restrict__ out, int n_nodes) {
    int warp_id = (blockIdx.x * blockDim.x + threadIdx.x) >> 5;
    if (warp_id >= n_nodes) return;
    int lane = threadIdx.x & 31;
    int half = lane >> 4;
    int c    = lane & 15;

    unsigned int start = g_offsets[warp_id];
    unsigned int end   = g_offsets[warp_id + 1];
    unsigned int deg   = end - start;

    const float NEG_INF = -__int_as_float(0x7f800000);
    float4 s  = {0.f, 0.f, 0.f, 0.f};
    float4 q  = {0.f, 0.f, 0.f, 0.f};
    float4 mx = {NEG_INF, NEG_INF, NEG_INF, NEG_INF};

    for (unsigned int i = start + half; i < end; i += 2) {
        int e = g_edge_sorted[i];
        float4 m = msg[(size_t)e * 16 + c];
        s.x += m.x;       s.y += m.y;       s.z += m.z;       s.w += m.w;
        q.x += m.x * m.x; q.y += m.y * m.y; q.z += m.z * m.z; q.w += m.w * m.w;
        mx.x = fmaxf(mx.x, m.x); mx.y = fmaxf(mx.y, m.y);
        mx.z = fmaxf(mx.z, m.z); mx.w = fmaxf(mx.w, m.w);
    }

    // combine the two half-warps (lane i <-> lane i+16 hold same feature cols)
    const unsigned FULL = 0xffffffffu;
    s.x += __shfl_xor_sync(FULL, s.x, 16); s.y += __shfl_xor_sync(FULL, s.y, 16);
    s.z += __shfl_xor_sync(FULL, s.z, 16); s.w += __shfl_xor_sync(FULL, s.w, 16);
    q.x += __shfl_xor_sync(FULL, q.x, 16); q.y += __shfl_xor_sync(FULL, q.y, 16);
    q.z += __shfl_xor_sync(FULL, q.z, 16); q.w += __shfl_xor_sync(FULL, q.w, 16);
    mx.x = fmaxf(mx.x, __shfl_xor_sync(FULL, mx.x, 16));
    mx.y = fmaxf(mx.y, __shfl_xor_sync(FULL, mx.y, 16));
    mx.z = fmaxf(mx.z, __shfl_xor_sync(FULL, mx.z, 16));
    mx.w = fmaxf(mx.w, __shfl_xor_sync(FULL, mx.w, 16));

    float degf = deg ? (float)deg : 1.0f;
    float inv  = 1.0f / degf;
    float4 mean = {s.x * inv, s.y * inv, s.z * inv, s.w * inv};
    float4 sd;
    sd.x = sqrtf(fmaxf(q.x * inv - mean.x * mean.x, 0.0f) + 1e-8f);
    sd.y = sqrtf(fmaxf(q.y * inv - mean.y * mean.y, 0.0f) + 1e-8f);
    sd.z = sqrtf(fmaxf(q.z * inv - mean.z * mean.z, 0.0f) + 1e-8f);
    sd.w = sqrtf(fmaxf(q.w * inv - mean.w * mean.w, 0.0f) + 1e-8f);
    if (deg == 0) { mx.x = mx.y = mx.z = mx.w = 0.0f; }  // empty segment -> 0

    // output row: [sum(64) | mean(64) | max(64) | std(64)]
    float4* row = (float4*)(out + (size_t)warp_id * (4 * D_FEAT));
    if (half == 0) {
        row[c]      = s;    // sum  at  [0..64)
        row[32 + c] = mx;   // max  at [128..192)
    } else {
        row[16 + c] = mean; // mean at [64..128)
        row[48 + c] = sd;   // std  at [192..256)
    }
}

extern "C" void kernel_launch(void* const* d_in, const int* in_sizes, int n_in,
                              void* d_out, int out_size) {
    const float* msg = (const float*)d_in[0];
    const int*   dst = (const int*)d_in[1];
    int n_edges = in_sizes[1];
    if (n_edges > MAX_EDGES) n_edges = MAX_EDGES;
    int n_nodes = out_size / (4 * D_FEAT);
    if (n_nodes > MAX_NODES) n_nodes = MAX_NODES;

    int scan_blocks = (n_nodes + 511) / 512;          // 196 for 100K (<=256)

    zero_cnt_kernel<<<(n_nodes + 511) / 512, 512>>>(n_nodes);
    hist_kernel<<<(n_edges + 511) / 512, 512>>>(dst, n_edges, n_nodes);
    scan1_kernel<<<scan_blocks, 512>>>(n_nodes);
    scan2_kernel<<<1, 256>>>(scan_blocks);
    scan3_kernel<<<scan_blocks, 512>>>(n_nodes, n_edges);
    scatter_ids_kernel<<<(n_edges + 511) / 512, 512>>>(dst, n_edges, n_nodes);

    int warps_needed = n_nodes;
    int gather_blocks = (warps_needed * 32 + 255) / 256;
    gather_kernel<<<gather_blocks, 256>>>((const float4*)msg, (float*)d_out, n_nodes);
}

// round 4
// speedup vs baseline: 3.0691x; 1.0492x over previous
#include <cuda_runtime.h>
#include <cstdint>

#define MAX_NODES 100000
#define MAX_EDGES 1600000
#define D_FEAT 64
#define SCAN_BLOCK 512
#define MAX_SCAN_BLOCKS 256

// ---- scratch ----
__device__ unsigned int       g_cnt        [MAX_NODES];
__device__ unsigned int       g_offsets    [MAX_NODES + 1];
__device__ unsigned int       g_cursor     [MAX_NODES];
__device__ unsigned long long g_desc       [MAX_SCAN_BLOCKS];  // lookback descriptors
__device__ int                g_edge_sorted[MAX_EDGES];

#define FLAG_INVALID 0ull
#define FLAG_AGG     1ull
#define FLAG_INC     2ull
__device__ __forceinline__ unsigned long long pack_desc(unsigned long long flag, unsigned int v) {
    return (flag << 32) | (unsigned long long)v;
}

// ---------------- pass 0: zero counters + descriptors ----------------
__global__ void zero_kernel(int n_nodes) {
    int i = blockIdx.x * blockDim.x + threadIdx.x;
    if (i < n_nodes) g_cnt[i] = 0u;
    if (i < MAX_SCAN_BLOCKS) g_desc[i] = FLAG_INVALID;
}

// ---------------- pass 1: histogram ----------------
__global__ void hist_kernel(const int* __restrict__ dst, int n_edges, int n_nodes) {
    int e = blockIdx.x * blockDim.x + threadIdx.x;
    if (e >= n_edges) return;
    int d = dst[e];
    if ((unsigned)d < (unsigned)n_nodes) atomicAdd(&g_cnt[d], 1u);
}

// ---------------- pass 2: single-kernel decoupled-lookback exclusive scan ----
// 512 threads/block; all blocks resident simultaneously (196 blocks << capacity),
// so the lookback spin cannot deadlock.
__global__ void __launch_bounds__(SCAN_BLOCK)
scan_lookback_kernel(int n_nodes, int n_edges) {
    __shared__ unsigned int sm_warp_tot[16];
    __shared__ unsigned int sm_excl_prefix;

    int tid  = threadIdx.x;
    int lane = tid & 31;
    int wid  = tid >> 5;
    int gi   = blockIdx.x * SCAN_BLOCK + tid;

    unsigned int v = (gi < n_nodes) ? g_cnt[gi] : 0u;

    // inclusive warp scan
    unsigned int inc = v;
    #pragma unroll
    for (int off = 1; off < 32; off <<= 1) {
        unsigned int t = __shfl_up_sync(0xffffffffu, inc, off);
        if (lane >= off) inc += t;
    }
    if (lane == 31) sm_warp_tot[wid] = inc;
    __syncthreads();

    // scan the 16 warp totals in warp 0
    if (wid == 0) {
        unsigned int w = (lane < 16) ? sm_warp_tot[lane] : 0u;
        unsigned int winc = w;
        #pragma unroll
        for (int off = 1; off < 16; off <<= 1) {
            unsigned int t = __shfl_up_sync(0xffffffffu, winc, off);
            if (lane >= off) winc += t;
        }
        if (lane < 16) sm_warp_tot[lane] = winc - w;   // exclusive warp offsets
    }
    __syncthreads();

    unsigned int local_excl = sm_warp_tot[wid] + inc - v;  // exclusive within block
    unsigned int block_agg;   // total of this block
    if (wid == 15) block_agg = __shfl_sync(0xffffffffu, inc, 31) + sm_warp_tot[15];
    // broadcast aggregate via smem (only warp 15 lane 31 has it)
    __shared__ unsigned int sm_agg;
    if (tid == SCAN_BLOCK - 1) sm_agg = sm_warp_tot[15] + inc;
    __syncthreads();
    block_agg = sm_agg;

    // publish descriptor
    if (tid == 0) {
        unsigned long long d = (blockIdx.x == 0)
            ? pack_desc(FLAG_INC, block_agg)
            : pack_desc(FLAG_AGG, block_agg);
        __threadfence();
        atomicExch(&g_desc[blockIdx.x], d);
    }

    // windowed lookback (warp 0)
    if (blockIdx.x == 0) {
        if (tid == 0) sm_excl_prefix = 0u;
    } else if (wid == 0) {
        unsigned int excl = 0u;
        int start = (int)blockIdx.x - 1;
        while (true) {
            int idx = start - lane;                 // lane 0 = nearest predecessor
            unsigned long long d;
            unsigned long long f;
            do {
                d = (idx >= 0) ? atomicAdd(&g_desc[idx], 0ull)
                               : pack_desc(FLAG_AGG, 0u);
                f = d >> 32;
            } while (__any_sync(0xffffffffu, f == FLAG_INVALID));
            unsigned int val = (unsigned int)d;
            unsigned int incmask = __ballot_sync(0xffffffffu, (idx >= 0) && f == FLAG_INC);
            unsigned int contrib;
            if (incmask) {
                int inc_lane = __ffs(incmask) - 1;  // nearest INC
                contrib = (lane <= inc_lane) ? val : 0u;
            } else {
                contrib = (idx >= 0) ? val : 0u;
            }
            #pragma unroll
            for (int off = 16; off > 0; off >>= 1)
                contrib += __shfl_xor_sync(0xffffffffu, contrib, off);
            excl += contrib;
            if (incmask) break;
            start -= 32;
        }
        if (lane == 0) {
            sm_excl_prefix = excl;
            __threadfence();
            atomicExch(&g_desc[blockIdx.x], pack_desc(FLAG_INC, excl + block_agg));
        }
    }
    __syncthreads();
    unsigned int excl_prefix = sm_excl_prefix;

    if (gi < n_nodes) {
        unsigned int o = excl_prefix + local_excl;
        g_offsets[gi] = o;
        g_cursor[gi]  = o;
    }
    if (gi == 0) g_offsets[n_nodes] = (unsigned int)n_edges;
}

// ---------------- pass 3: scatter edge ids into sorted order ----------------
__global__ void scatter_ids_kernel(const int* __restrict__ dst, int n_edges, int n_nodes) {
    int e = blockIdx.x * blockDim.x + threadIdx.x;
    if (e >= n_edges) return;
    int d = dst[e];
    if ((unsigned)d >= (unsigned)n_nodes) return;
    unsigned int pos = atomicAdd(&g_cursor[d], 1u);
    g_edge_sorted[pos] = e;
}

// ---------------- pass 4: gather + reduce in registers ----------------
// One warp per node; each half-warp streams one edge row per step (16 lanes x
// float4 = 256B coalesced). Manual 2x unroll for memory-level parallelism.
__global__ void gather_kernel(const float4* __restrict__ msg,
                              float* __restrict__ out, int n_nodes) {
    int warp_id = (blockIdx.x * blockDim.x + threadIdx.x) >> 5;
    if (warp_id >= n_nodes) return;
    int lane = threadIdx.x & 31;
    int half = lane >> 4;
    int c    = lane & 15;

    unsigned int start = g_offsets[warp_id];
    unsigned int end   = g_offsets[warp_id + 1];
    unsigned int deg   = end - start;

    const float NEG_INF = -__int_as_float(0x7f800000);
    float4 s  = {0.f, 0.f, 0.f, 0.f};
    float4 q  = {0.f, 0.f, 0.f, 0.f};
    float4 mx = {NEG_INF, NEG_INF, NEG_INF, NEG_INF};

    unsigned int i = start + half;
    // unrolled by 2: two independent edge loads in flight per half-warp
    for (; i + 2 < end; i += 4) {
        int e0 = g_edge_sorted[i];
        int e1 = g_edge_sorted[i + 2];
        float4 m0 = msg[(size_t)e0 * 16 + c];
        float4 m1 = msg[(size_t)e1 * 16 + c];
        s.x += m0.x + m1.x; s.y += m0.y + m1.y;
        s.z += m0.z + m1.z; s.w += m0.w + m1.w;
        q.x += m0.x * m0.x + m1.x * m1.x; q.y += m0.y * m0.y + m1.y * m1.y;
        q.z += m0.z * m0.z + m1.z * m1.z; q.w += m0.w * m0.w + m1.w * m1.w;
        mx.x = fmaxf(mx.x, fmaxf(m0.x, m1.x)); mx.y = fmaxf(mx.y, fmaxf(m0.y, m1.y));
        mx.z = fmaxf(mx.z, fmaxf(m0.z, m1.z)); mx.w = fmaxf(mx.w, fmaxf(m0.w, m1.w));
    }
    for (; i < end; i += 2) {
        int e = g_edge_sorted[i];
        float4 m = msg[(size_t)e * 16 + c];
        s.x += m.x;       s.y += m.y;       s.z += m.z;       s.w += m.w;
        q.x += m.x * m.x; q.y += m.y * m.y; q.z += m.z * m.z; q.w += m.w * m.w;
        mx.x = fmaxf(mx.x, m.x); mx.y = fmaxf(mx.y, m.y);
        mx.z = fmaxf(mx.z, m.z); mx.w = fmaxf(mx.w, m.w);
    }

    const unsigned FULL = 0xffffffffu;
    s.x += __shfl_xor_sync(FULL, s.x, 16); s.y += __shfl_xor_sync(FULL, s.y, 16);
    s.z += __shfl_xor_sync(FULL, s.z, 16); s.w += __shfl_xor_sync(FULL, s.w, 16);
    q.x += __shfl_xor_sync(FULL, q.x, 16); q.y += __shfl_xor_sync(FULL, q.y, 16);
    q.z += __shfl_xor_sync(FULL, q.z, 16); q.w += __shfl_xor_sync(FULL, q.w, 16);
    mx.x = fmaxf(mx.x, __shfl_xor_sync(FULL, mx.x, 16));
    mx.y = fmaxf(mx.y, __shfl_xor_sync(FULL, mx.y, 16));
    mx.z = fmaxf(mx.z, __shfl_xor_sync(FULL, mx.z, 16));
    mx.w = fmaxf(mx.w, __shfl_xor_sync(FULL, mx.w, 16));

    float degf = deg ? (float)deg : 1.0f;
    float inv  = 1.0f / degf;
    float4 mean = {s.x * inv, s.y * inv, s.z * inv, s.w * inv};
    float4 sd;
    sd.x = sqrtf(fmaxf(q.x * inv - mean.x * mean.x, 0.0f) + 1e-8f);
    sd.y = sqrtf(fmaxf(q.y * inv - mean.y * mean.y, 0.0f) + 1e-8f);
    sd.z = sqrtf(fmaxf(q.z * inv - mean.z * mean.z, 0.0f) + 1e-8f);
    sd.w = sqrtf(fmaxf(q.w * inv - mean.w * mean.w, 0.0f) + 1e-8f);
    if (deg == 0) { mx.x = mx.y = mx.z = mx.w = 0.0f; }

    float4* row = (float4*)(out + (size_t)warp_id * (4 * D_FEAT));
    if (half == 0) {
        row[c]      = s;    // sum  [0..64)
        row[32 + c] = mx;   // max  [128..192)
    } else {
        row[16 + c] = mean; // mean [64..128)
        row[48 + c] = sd;   // std  [192..256)
    }
}

extern "C" void kernel_launch(void* const* d_in, const int* in_sizes, int n_in,
                              void* d_out, int out_size) {
    const float* msg = (const float*)d_in[0];
    const int*   dst = (const int*)d_in[1];
    int n_edges = in_sizes[1];
    if (n_edges > MAX_EDGES) n_edges = MAX_EDGES;
    int n_nodes = out_size / (4 * D_FEAT);
    if (n_nodes > MAX_NODES) n_nodes = MAX_NODES;

    int scan_blocks = (n_nodes + SCAN_BLOCK - 1) / SCAN_BLOCK;   // 196 for 100K

    zero_kernel<<<(n_nodes + 511) / 512, 512>>>(n_nodes);
    hist_kernel<<<(n_edges + 511) / 512, 512>>>(dst, n_edges, n_nodes);
    scan_lookback_kernel<<<scan_blocks, SCAN_BLOCK>>>(n_nodes, n_edges);
    scatter_ids_kernel<<<(n_edges + 511) / 512, 512>>>(dst, n_edges, n_nodes);

    int gather_blocks = (n_nodes * 32 + 255) / 256;
    gather_kernel<<<gather_blocks, 256>>>((const float4*)msg, (float*)d_out, n_nodes);
}

// round 5
// speedup vs baseline: 3.1338x; 1.0211x over previous
#include <cuda_runtime.h>
#include <cstdint>

#define MAX_NODES 100000
#define MAX_EDGES 1600000
#define D_FEAT 64
#define SCAN_BLOCK 512
#define MAX_SCAN_BLOCKS 256

// ---- scratch (all zero-initialized at module load; invariants below keep
//      g_cnt and g_desc zeroed at the END of every kernel_launch run) ----
__device__ unsigned int       g_cnt        [MAX_NODES];
__device__ unsigned int       g_offsets    [MAX_NODES + 1];
__device__ unsigned long long g_desc       [MAX_SCAN_BLOCKS];
__device__ int                g_rank       [MAX_EDGES];
__device__ int                g_edge_sorted[MAX_EDGES];

#define FLAG_INVALID 0ull
#define FLAG_AGG     1ull
#define FLAG_INC     2ull
__device__ __forceinline__ unsigned long long pack_desc(unsigned long long flag, unsigned int v) {
    return (flag << 32) | (unsigned long long)v;
}

// ---------------- pass 1: rank (the ONLY atomic pass) ----------------
// rank[e] = arrival order of edge e at its destination node; also builds the
// histogram in g_cnt. 4 edges per thread via int4 for memory-level parallelism.
__global__ void rank_kernel(const int* __restrict__ dst, int n_edges, int n_nodes) {
    int i4 = blockIdx.x * blockDim.x + threadIdx.x;
    int base = i4 * 4;
    if (base + 3 < n_edges) {
        int4 d = ((const int4*)dst)[i4];
        int4 r;
        r.x = ((unsigned)d.x < (unsigned)n_nodes) ? (int)atomicAdd(&g_cnt[d.x], 1u) : 0;
        r.y = ((unsigned)d.y < (unsigned)n_nodes) ? (int)atomicAdd(&g_cnt[d.y], 1u) : 0;
        r.z = ((unsigned)d.z < (unsigned)n_nodes) ? (int)atomicAdd(&g_cnt[d.z], 1u) : 0;
        r.w = ((unsigned)d.w < (unsigned)n_nodes) ? (int)atomicAdd(&g_cnt[d.w], 1u) : 0;
        ((int4*)g_rank)[i4] = r;
    } else {
        for (int e = base; e < n_edges; e++) {
            int d = dst[e];
            g_rank[e] = ((unsigned)d < (unsigned)n_nodes)
                      ? (int)atomicAdd(&g_cnt[d], 1u) : 0;
        }
    }
}

// ---------------- pass 2: decoupled-lookback exclusive scan ----------------
__global__ void __launch_bounds__(SCAN_BLOCK)
scan_lookback_kernel(int n_nodes, int n_edges) {
    __shared__ unsigned int sm_warp_tot[16];
    __shared__ unsigned int sm_excl_prefix;
    __shared__ unsigned int sm_agg;

    int tid  = threadIdx.x;
    int lane = tid & 31;
    int wid  = tid >> 5;
    int gi   = blockIdx.x * SCAN_BLOCK + tid;

    unsigned int v = (gi < n_nodes) ? g_cnt[gi] : 0u;

    unsigned int inc = v;
    #pragma unroll
    for (int off = 1; off < 32; off <<= 1) {
        unsigned int t = __shfl_up_sync(0xffffffffu, inc, off);
        if (lane >= off) inc += t;
    }
    if (lane == 31) sm_warp_tot[wid] = inc;
    __syncthreads();

    if (wid == 0) {
        unsigned int w = (lane < 16) ? sm_warp_tot[lane] : 0u;
        unsigned int winc = w;
        #pragma unroll
        for (int off = 1; off < 16; off <<= 1) {
            unsigned int t = __shfl_up_sync(0xffffffffu, winc, off);
            if (lane >= off) winc += t;
        }
        if (lane < 16) sm_warp_tot[lane] = winc - w;
    }
    __syncthreads();

    unsigned int local_excl = sm_warp_tot[wid] + inc - v;
    if (tid == SCAN_BLOCK - 1) sm_agg = sm_warp_tot[15] + inc;
    __syncthreads();
    unsigned int block_agg = sm_agg;

    if (tid == 0) {
        unsigned long long d = (blockIdx.x == 0)
            ? pack_desc(FLAG_INC, block_agg)
            : pack_desc(FLAG_AGG, block_agg);
        __threadfence();
        atomicExch(&g_desc[blockIdx.x], d);
    }

    if (blockIdx.x == 0) {
        if (tid == 0) sm_excl_prefix = 0u;
    } else if (wid == 0) {
        unsigned int excl = 0u;
        int start = (int)blockIdx.x - 1;
        while (true) {
            int idx = start - lane;
            unsigned long long d;
            unsigned long long f;
            do {
                d = (idx >= 0) ? atomicAdd(&g_desc[idx], 0ull)
                               : pack_desc(FLAG_AGG, 0u);
                f = d >> 32;
            } while (__any_sync(0xffffffffu, f == FLAG_INVALID));
            unsigned int val = (unsigned int)d;
            unsigned int incmask = __ballot_sync(0xffffffffu, (idx >= 0) && f == FLAG_INC);
            unsigned int contrib;
            if (incmask) {
                int inc_lane = __ffs(incmask) - 1;
                contrib = (lane <= inc_lane) ? val : 0u;
            } else {
                contrib = (idx >= 0) ? val : 0u;
            }
            #pragma unroll
            for (int off = 16; off > 0; off >>= 1)
                contrib += __shfl_xor_sync(0xffffffffu, contrib, off);
            excl += contrib;
            if (incmask) break;
            start -= 32;
        }
        if (lane == 0) {
            sm_excl_prefix = excl;
            __threadfence();
            atomicExch(&g_desc[blockIdx.x], pack_desc(FLAG_INC, excl + block_agg));
        }
    }
    __syncthreads();
    unsigned int excl_prefix = sm_excl_prefix;

    if (gi < n_nodes) g_offsets[gi] = excl_prefix + local_excl;
    if (gi == 0)      g_offsets[n_nodes] = (unsigned int)n_edges;
}

// ---------------- pass 3: place (atomic-free) + cleanup for next run -------
// edge_sorted[offsets[d] + rank[e]] = e. Also re-zeroes g_cnt and g_desc so
// the next replay starts from the module-load invariant (deterministic: every
// run does identical work and leaves identical state).
__global__ void place_kernel(const int* __restrict__ dst, int n_edges, int n_nodes) {
    int i4 = blockIdx.x * blockDim.x + threadIdx.x;
    int base = i4 * 4;
    if (base + 3 < n_edges) {
        int4 d = ((const int4*)dst)[i4];
        int4 r = ((const int4*)g_rank)[i4];
        if ((unsigned)d.x < (unsigned)n_nodes) g_edge_sorted[g_offsets[d.x] + r.x] = base;
        if ((unsigned)d.y < (unsigned)n_nodes) g_edge_sorted[g_offsets[d.y] + r.y] = base + 1;
        if ((unsigned)d.z < (unsigned)n_nodes) g_edge_sorted[g_offsets[d.z] + r.z] = base + 2;
        if ((unsigned)d.w < (unsigned)n_nodes) g_edge_sorted[g_offsets[d.w] + r.w] = base + 3;
    } else {
        for (int e = base; e < n_edges; e++) {
            int d = dst[e];
            if ((unsigned)d < (unsigned)n_nodes)
                g_edge_sorted[g_offsets[d] + g_rank[e]] = e;
        }
    }
    // cleanup (runs after scan has consumed g_cnt / g_desc)
    int t = blockIdx.x * blockDim.x + threadIdx.x;
    if (t < n_nodes) g_cnt[t] = 0u;
    if (t < MAX_SCAN_BLOCKS) g_desc[t] = FLAG_INVALID;
}

// ---------------- pass 4: gather + reduce in registers ----------------
// One warp per node; each half-warp streams one edge row per step (16 lanes x
// float4 = 256B coalesced). 4x unroll for deep memory-level parallelism.
__global__ void gather_kernel(const float4* __restrict__ msg,
                              float* __restrict__ out, int n_nodes) {
    int warp_id = (blockIdx.x * blockDim.x + threadIdx.x) >> 5;
    if (warp_id >= n_nodes) return;
    int lane = threadIdx.x & 31;
    int half = lane >> 4;
    int c    = lane & 15;

    unsigned int start = g_offsets[warp_id];
    unsigned int end   = g_offsets[warp_id + 1];
    unsigned int deg   = end - start;

    const float NEG_INF = -__int_as_float(0x7f800000);
    float4 s  = {0.f, 0.f, 0.f, 0.f};
    float4 q  = {0.f, 0.f, 0.f, 0.f};
    float4 mx = {NEG_INF, NEG_INF, NEG_INF, NEG_INF};

    unsigned int i = start + half;
    // 4 independent edge rows in flight per half-warp
    for (; i + 6 < end; i += 8) {
        int e0 = g_edge_sorted[i];
        int e1 = g_edge_sorted[i + 2];
        int e2 = g_edge_sorted[i + 4];
        int e3 = g_edge_sorted[i + 6];
        float4 m0 = msg[(size_t)e0 * 16 + c];
        float4 m1 = msg[(size_t)e1 * 16 + c];
        float4 m2 = msg[(size_t)e2 * 16 + c];
        float4 m3 = msg[(size_t)e3 * 16 + c];
        s.x += (m0.x + m1.x) + (m2.x + m3.x);
        s.y += (m0.y + m1.y) + (m2.y + m3.y);
        s.z += (m0.z + m1.z) + (m2.z + m3.z);
        s.w += (m0.w + m1.w) + (m2.w + m3.w);
        q.x += (m0.x*m0.x + m1.x*m1.x) + (m2.x*m2.x + m3.x*m3.x);
        q.y += (m0.y*m0.y + m1.y*m1.y) + (m2.y*m2.y + m3.y*m3.y);
        q.z += (m0.z*m0.z + m1.z*m1.z) + (m2.z*m2.z + m3.z*m3.z);
        q.w += (m0.w*m0.w + m1.w*m1.w) + (m2.w*m2.w + m3.w*m3.w);
        mx.x = fmaxf(mx.x, fmaxf(fmaxf(m0.x, m1.x), fmaxf(m2.x, m3.x)));
        mx.y = fmaxf(mx.y, fmaxf(fmaxf(m0.y, m1.y), fmaxf(m2.y, m3.y)));
        mx.z = fmaxf(mx.z, fmaxf(fmaxf(m0.z, m1.z), fmaxf(m2.z, m3.z)));
        mx.w = fmaxf(mx.w, fmaxf(fmaxf(m0.w, m1.w), fmaxf(m2.w, m3.w)));
    }
    for (; i < end; i += 2) {
        int e = g_edge_sorted[i];
        float4 m = msg[(size_t)e * 16 + c];
        s.x += m.x;       s.y += m.y;       s.z += m.z;       s.w += m.w;
        q.x += m.x * m.x; q.y += m.y * m.y; q.z += m.z * m.z; q.w += m.w * m.w;
        mx.x = fmaxf(mx.x, m.x); mx.y = fmaxf(mx.y, m.y);
        mx.z = fmaxf(mx.z, m.z); mx.w = fmaxf(mx.w, m.w);
    }

    const unsigned FULL = 0xffffffffu;
    s.x += __shfl_xor_sync(FULL, s.x, 16); s.y += __shfl_xor_sync(FULL, s.y, 16);
    s.z += __shfl_xor_sync(FULL, s.z, 16); s.w += __shfl_xor_sync(FULL, s.w, 16);
    q.x += __shfl_xor_sync(FULL, q.x, 16); q.y += __shfl_xor_sync(FULL, q.y, 16);
    q.z += __shfl_xor_sync(FULL, q.z, 16); q.w += __shfl_xor_sync(FULL, q.w, 16);
    mx.x = fmaxf(mx.x, __shfl_xor_sync(FULL, mx.x, 16));
    mx.y = fmaxf(mx.y, __shfl_xor_sync(FULL, mx.y, 16));
    mx.z = fmaxf(mx.z, __shfl_xor_sync(FULL, mx.z, 16));
    mx.w = fmaxf(mx.w, __shfl_xor_sync(FULL, mx.w, 16));

    float degf = deg ? (float)deg : 1.0f;
    float inv  = 1.0f / degf;
    float4 mean = {s.x * inv, s.y * inv, s.z * inv, s.w * inv};
    float4 sd;
    sd.x = sqrtf(fmaxf(q.x * inv - mean.x * mean.x, 0.0f) + 1e-8f);
    sd.y = sqrtf(fmaxf(q.y * inv - mean.y * mean.y, 0.0f) + 1e-8f);
    sd.z = sqrtf(fmaxf(q.z * inv - mean.z * mean.z, 0.0f) + 1e-8f);
    sd.w = sqrtf(fmaxf(q.w * inv - mean.w * mean.w, 0.0f) + 1e-8f);
    if (deg == 0) { mx.x = mx.y = mx.z = mx.w = 0.0f; }

    float4* row = (float4*)(out + (size_t)warp_id * (4 * D_FEAT));
    if (half == 0) {
        row[c]      = s;    // sum  [0..64)
        row[32 + c] = mx;   // max  [128..192)
    } else {
        row[16 + c] = mean; // mean [64..128)
        row[48 + c] = sd;   // std  [192..256)
    }
}

extern "C" void kernel_launch(void* const* d_in, const int* in_sizes, int n_in,
                              void* d_out, int out_size) {
    const float* msg = (const float*)d_in[0];
    const int*   dst = (const int*)d_in[1];
    int n_edges = in_sizes[1];
    if (n_edges > MAX_EDGES) n_edges = MAX_EDGES;
    int n_nodes = out_size / (4 * D_FEAT);
    if (n_nodes > MAX_NODES) n_nodes = MAX_NODES;

    int scan_blocks = (n_nodes + SCAN_BLOCK - 1) / SCAN_BLOCK;

    int quads = (n_edges + 3) / 4;
    rank_kernel<<<(quads + 255) / 256, 256>>>(dst, n_edges, n_nodes);
    scan_lookback_kernel<<<scan_blocks, SCAN_BLOCK>>>(n_nodes, n_edges);
    place_kernel<<<(quads + 255) / 256, 256>>>(dst, n_edges, n_nodes);

    int gather_blocks = (n_nodes * 32 + 255) / 256;
    gather_kernel<<<gather_blocks, 256>>>((const float4*)msg, (float*)d_out, n_nodes);
}